// round 1
// baseline (speedup 1.0000x reference)
#include <cuda_runtime.h>

// Problem constants (fixed shapes from reference)
#define BB 8
#define SS 4096
#define DD 1024
#define HH 12

// Scratch: wave[t] for t in [0, S)
__device__ float g_wave[SS];

// Kernel 1: compute wave[t] = mean_i amp[i] * sin(2*pi*f_i*(time + t/S))
// Replicates the reference's fp32 arithmetic order:
//   c_i = (2*pi) * f_i   (fp32)
//   phase = c_i * (time + t/S)  (fp32)
__global__ void wave_kernel(const float* __restrict__ freqs,
                            const float* __restrict__ amps,
                            const float* __restrict__ time_p) {
    int t = blockIdx.x * blockDim.x + threadIdx.x;
    if (t >= SS) return;
    float tm = *time_p;
    float arg = tm + (float)t / (float)SS;
    float acc = 0.0f;
    #pragma unroll
    for (int i = 0; i < HH; i++) {
        float c = 6.283185307179586f * freqs[i];  // fp32 round, same as XLA
        acc += amps[i] * sinf(c * arg);
    }
    g_wave[t] = acc / (float)HH;
}

// Kernel 2: pure streaming multiply, float4-vectorized.
// Flat float4 index: d4 in [0,256), s in [0,4096), b in [0,8)
//   id = ((b*SS + s) * 256) + d4   ->  s = (id >> 8) & 4095
__global__ void scale_kernel(const float4* __restrict__ x,
                             float4* __restrict__ out) {
    unsigned int id = blockIdx.x * blockDim.x + threadIdx.x;
    // total float4 = 8*4096*256 = 8388608; grid sized exactly, no bounds check needed
    float w = g_wave[(id >> 8) & (SS - 1)];
    float4 v = x[id];
    v.x *= w; v.y *= w; v.z *= w; v.w *= w;
    out[id] = v;
}

extern "C" void kernel_launch(void* const* d_in, const int* in_sizes, int n_in,
                              void* d_out, int out_size) {
    const float* x     = (const float*)d_in[0];
    const float* freqs = (const float*)d_in[1];
    const float* amps  = (const float*)d_in[2];
    const float* timep = (const float*)d_in[3];
    float* out = (float*)d_out;

    wave_kernel<<<(SS + 255) / 256, 256>>>(freqs, amps, timep);

    const unsigned int total4 = (unsigned int)BB * SS * (DD / 4); // 8388608
    scale_kernel<<<total4 / 256, 256>>>((const float4*)x, (float4*)out);
}

// round 2
// speedup vs baseline: 1.0532x; 1.0532x over previous
#include <cuda_runtime.h>

// Fixed shapes: B=8, S=4096, D=1024, H=12
#define SS 4096
#define ROWS_PER_BLOCK 8
#define F4_PER_ROW 256   // D/4

// One block = 8 contiguous rows (8 * 1024 floats = 2048 float4).
// Threads 0-7 compute the per-row wave into smem (overlapped with the
// front-batched data loads); then all 256 threads do 8 multiply-stores.
__global__ void __launch_bounds__(256) fused_resonance_kernel(
    const float4* __restrict__ x,
    float4* __restrict__ out,
    const float* __restrict__ freqs,
    const float* __restrict__ amps,
    const float* __restrict__ time_p)
{
    __shared__ float s_w[ROWS_PER_BLOCK];

    const unsigned int tid  = threadIdx.x;
    const unsigned int row0 = blockIdx.x * ROWS_PER_BLOCK;
    const unsigned int base = row0 * F4_PER_ROW + tid;

    // Front-batch 8 independent streaming loads (MLP_p1 = 8)
    float4 v[ROWS_PER_BLOCK];
    #pragma unroll
    for (int j = 0; j < ROWS_PER_BLOCK; j++) {
        v[j] = __ldcs(&x[base + j * F4_PER_ROW]);
    }

    // While loads are in flight: 8 threads compute wave[s] for this block's rows.
    // Exact fp32 op order of the reference:
    //   c_i = (2*pi)*f_i  (fp32 round); phase = c_i*(time + s/S); sum/12
    if (tid < ROWS_PER_BLOCK) {
        const unsigned int s = (row0 + tid) & (SS - 1);
        const float arg = *time_p + (float)s / (float)SS;
        float acc = 0.0f;
        #pragma unroll
        for (int i = 0; i < 12; i++) {
            float c = 6.283185307179586f * freqs[i];
            acc += amps[i] * sinf(c * arg);
        }
        s_w[tid] = acc / 12.0f;
    }
    __syncthreads();

    #pragma unroll
    for (int j = 0; j < ROWS_PER_BLOCK; j++) {
        const float w = s_w[j];
        float4 r = v[j];
        r.x *= w; r.y *= w; r.z *= w; r.w *= w;
        __stcs(&out[base + j * F4_PER_ROW], r);
    }
}

extern "C" void kernel_launch(void* const* d_in, const int* in_sizes, int n_in,
                              void* d_out, int out_size) {
    const float* x     = (const float*)d_in[0];
    const float* freqs = (const float*)d_in[1];
    const float* amps  = (const float*)d_in[2];
    const float* timep = (const float*)d_in[3];
    float* out = (float*)d_out;

    // total rows = B*S = 32768; 8 rows per block -> 4096 blocks
    fused_resonance_kernel<<<4096, 256>>>(
        (const float4*)x, (float4*)out, freqs, amps, timep);
}